// round 12
// baseline (speedup 1.0000x reference)
#include <cuda_runtime.h>

// DirichletLoss: ball query (r=0.15, K=32 nearest within radius) + neighbor
// feature variance, mean over all B*N queries, *0.5.
//
// 5-kernel pipeline (graph-capturable, scratch in __device__ globals):
//   k_zero    : clear cell counters + reduction ticket
//   k_hist    : 64-block histogram into anisotropic grid 7(z)x7(y)x32(x)
//   k_scan    : single-block global exclusive scan (13 cells/thread)
//   k_scatter : counting-sort points into float4(x,y,z,f), cell-major
//   k_main    : warp-per-query, single pass. Packed keys
//               uint32 = (d2 bits & ~0xFFF) | batch-local index.
//               First chunk: 32-lane bitonic sort free-fills all slots.
//               Later chunks: ballot-filtered sorted insert (2 shfl each).
//               x-range clipped to [p.x-r, p.x+r] via fine x-cells.
//               Block partial -> last-block deterministic reduction -> out.
//
// All candidate ranges are clamped so every loop terminates even if the
// offset table were corrupt (bugs become wrong answers, not hangs).

#define FULLMASK 0xFFFFFFFFu

constexpr int   B    = 8;
constexpr int   N    = 4096;
constexpr int   BN   = B * N;
constexpr int   GDY  = 7;              // y,z cells (size 0.15 = r)
constexpr int   GDX  = 32;             // fine x cells (size 1/32)
constexpr int   NC   = GDY * GDY * GDX;  // 1568 cells per batch
constexpr int   TOTC = B * NC;           // 12544
constexpr int   NBLK = BN / 8;         // k_main blocks (8 warps each)
constexpr float R        = 0.15f;
constexpr float R2       = 0.15f * 0.15f;
constexpr float INV_YZ   = 1.0f / 0.15f;
constexpr unsigned SENT  = 0xFFFFFFFFu;

__device__ int      g_cnt[TOTC];
__device__ int      g_cur[TOTC];
__device__ int      g_off[TOTC + 1];
__device__ float4   g_pts[BN];         // (x,y,z,f) sorted by global cell id
__device__ float    g_var[NBLK];       // per-block partial sums
__device__ unsigned g_done;            // last-block ticket

__device__ __forceinline__ int cellyz(float v) {
    int c = (int)(v * INV_YZ);
    c = c < 0 ? 0 : c;
    return c > GDY - 1 ? GDY - 1 : c;
}
__device__ __forceinline__ int cellx(float v) {
    int c = (int)(v * (float)GDX);
    c = c < 0 ? 0 : c;
    return c > GDX - 1 ? GDX - 1 : c;
}
__device__ __forceinline__ int cellid(float x, float y, float z) {
    return (cellyz(z) * GDY + cellyz(y)) * GDX + cellx(x);
}

__global__ void k_zero() {
    int i = blockIdx.x * blockDim.x + threadIdx.x;
    if (i < TOTC) g_cnt[i] = 0;
    if (i == 0) g_done = 0;
}

__global__ void k_hist(const float* __restrict__ pos) {
    int i = blockIdx.x * 512 + threadIdx.x;      // grid 64 x 512 = BN
    float x = pos[3 * i], y = pos[3 * i + 1], z = pos[3 * i + 2];
    int b = i >> 12;
    atomicAdd(&g_cnt[b * NC + cellid(x, y, z)], 1);
}

// Global exclusive scan over TOTC=12544 counts: 1024 threads x 13 cells.
__global__ void __launch_bounds__(1024) k_scan() {
    __shared__ int wt[32], wb[32];
    int t = threadIdx.x, lane = t & 31, w = t >> 5;
    int c[13];
    int b0 = t * 13, s = 0;
    #pragma unroll
    for (int e = 0; e < 13; e++) {
        int i = b0 + e;
        c[e] = (i < TOTC) ? g_cnt[i] : 0;
        s += c[e];
    }
    int v = s;
    #pragma unroll
    for (int d = 1; d < 32; d <<= 1) {
        int u = __shfl_up_sync(FULLMASK, v, d);
        if (lane >= d) v += u;
    }
    if (lane == 31) wt[w] = v;
    __syncthreads();
    if (w == 0) {
        int x = wt[lane];                        // exactly 32 warps
        int vv = x;
        #pragma unroll
        for (int d = 1; d < 32; d <<= 1) {
            int u = __shfl_up_sync(FULLMASK, vv, d);
            if (lane >= d) vv += u;
        }
        wb[lane] = vv - x;                       // exclusive warp base
    }
    __syncthreads();
    int run = wb[w] + v - s;                     // thread's exclusive start
    #pragma unroll
    for (int e = 0; e < 13; e++) {
        int i = b0 + e;
        if (i < TOTC) { g_off[i] = run; g_cur[i] = run; run += c[e]; }
    }
    if (t == 0) g_off[TOTC] = BN;
}

__global__ void k_scatter(const float* __restrict__ pos,
                          const float* __restrict__ f) {
    int i = blockIdx.x * 512 + threadIdx.x;      // grid 64 x 512 = BN
    float x = pos[3 * i], y = pos[3 * i + 1], z = pos[3 * i + 2];
    int b = i >> 12;
    int cid = b * NC + cellid(x, y, z);
    int dst = atomicAdd(&g_cur[cid], 1);
    if (dst >= 0 && dst < BN)
        g_pts[dst] = make_float4(x, y, z, f[i]);
}

// One warp per query; bitonic first-chunk fill + sorted-insert top-32.
__global__ void __launch_bounds__(256) k_main(float* __restrict__ out) {
    __shared__ float  swarp[8];
    __shared__ double sd[256];
    __shared__ bool   amLast;
    int lane = threadIdx.x & 31;
    int wid  = threadIdx.x >> 5;
    int q    = blockIdx.x * 8 + wid;

    float4 p = g_pts[q];
    int b    = q >> 12;               // scan is batch-major -> contiguous
    int base = b * N;
    const float4* pbase = g_pts + base;
    int cy = cellyz(p.y), cz = cellyz(p.z);
    int xl = cellx(p.x - R), xh = cellx(p.x + R);   // exact x window

    // Key domain: pk = (d2 bits & ~0xFFF) | local index (12 bits).
    const unsigned cutR  = (__float_as_uint(R2) & 0xFFFFF000u) | 0xFFFu;
    const unsigned EMPTY = cutR + 1;

    // Lane-parallel preload of the 9 stencil row ranges (batch-relative,
    // clamped). Center row (dz=0,dy=0) first so the cutoff tightens early.
    int rs0 = 0, rs1 = 0;
    {
        const signed char DZ[9] = {0, 0, 0, -1, -1, -1, 1, 1, 1};
        const signed char DY[9] = {0, -1, 1, 0, -1, 1, 0, -1, 1};
        if (lane < 9) {
            int z = cz + DZ[lane], y = cy + DY[lane];
            if (z >= 0 && z < GDY && y >= 0 && y < GDY) {
                int rb = b * NC + (z * GDY + y) * GDX;
                int a0 = g_off[rb + xl] - base;
                int a1 = g_off[rb + xh + 1] - base;  // contiguous x cells
                a0 = a0 < 0 ? 0 : a0;                // termination guards
                a1 = a1 > N ? N : a1;
                rs0 = a0;
                rs1 = a1 < a0 ? a0 : a1;
            }
        }
    }

    unsigned kk = SENT;               // lane-sorted ascending packed keys
    unsigned cutoffC = EMPTY;         // min(lane31 key, EMPTY)
    bool firstChunk = true;           // warp-uniform

    #pragma unroll 1
    for (int r = 0; r < 9; r++) {
        int l0 = __shfl_sync(FULLMASK, rs0, r);
        int l1 = __shfl_sync(FULLMASK, rs1, r);
        for (int c0 = l0; c0 < l1; c0 += 32) {
            int l = c0 + lane;
            unsigned pk = SENT;
            if (l < l1) {
                float4 c = pbase[l];
                float dx = c.x - p.x, dy = c.y - p.y, dz = c.z - p.z;
                float d2 = fmaf(dx, dx, fmaf(dy, dy, dz * dz));
                pk = (__float_as_uint(d2) & 0xFFFFF000u) | (unsigned)l;
            }
            if (firstChunk) {
                // Full-warp bitonic ascending sort free-fills all 32 slots.
                unsigned v = pk;
                #pragma unroll
                for (int k = 2; k <= 32; k <<= 1) {
                    #pragma unroll
                    for (int j = k >> 1; j > 0; j >>= 1) {
                        unsigned o = __shfl_xor_sync(FULLMASK, v, j);
                        bool up    = ((lane & k) == 0);
                        bool lower = ((lane & j) == 0);
                        unsigned mn = o < v ? o : v;
                        unsigned mx = o < v ? v : o;
                        v = (lower == up) ? mn : mx;
                    }
                }
                kk = v;
                unsigned k31 = __shfl_sync(FULLMASK, kk, 31);
                cutoffC = k31 < EMPTY ? k31 : EMPTY;
                firstChunk = false;
                continue;
            }
            unsigned want = __ballot_sync(FULLMASK, pk < cutoffC);
            if (want) {
                do {
                    int src = __ffs(want) - 1;
                    want &= want - 1;
                    unsigned v  = __shfl_sync(FULLMASK, pk, src);
                    unsigned pd = __shfl_up_sync(FULLMASK, kk, 1);
                    if (lane == 0) pd = 0u;
                    if (kk > v) kk = pd > v ? pd : v;   // sorted insert
                } while (want);
                unsigned k31 = __shfl_sync(FULLMASK, kk, 31);
                cutoffC = k31 < EMPTY ? k31 : EMPTY;
            }
        }
    }

    // Epilogue: each lane holds one selected neighbor (or none).
    float acc = 0.0f;
    if (kk <= cutR) {
        int l = (int)(kk & 0xFFFu);
        float fj = pbase[l].w;
        float df = p.w - fj;
        acc = df * df;
    }
    #pragma unroll
    for (int o = 16; o; o >>= 1) acc += __shfl_xor_sync(FULLMASK, acc, o);
    if (lane == 0) swarp[wid] = acc;
    __syncthreads();
    if (threadIdx.x == 0) {
        float s = 0.0f;
        #pragma unroll
        for (int w = 0; w < 8; w++) s += swarp[w];
        g_var[blockIdx.x] = s;
    }

    // ---- last-block deterministic reduction ----
    __threadfence();
    if (threadIdx.x == 0)
        amLast = (atomicAdd(&g_done, 1u) == (unsigned)(NBLK - 1));
    __syncthreads();
    if (amLast) {
        double a = 0.0;
        for (int i = threadIdx.x; i < NBLK; i += 256) a += (double)g_var[i];
        sd[threadIdx.x] = a;
        __syncthreads();
        for (int d = 128; d; d >>= 1) {
            if (threadIdx.x < d) sd[threadIdx.x] += sd[threadIdx.x + d];
            __syncthreads();
        }
        if (threadIdx.x == 0) out[0] = (float)(0.5 * sd[0] / (double)BN);
    }
}

extern "C" void kernel_launch(void* const* d_in, const int* in_sizes, int n_in,
                              void* d_out, int out_size) {
    const float* pos = (const float*)d_in[0];
    const float* f   = (const float*)d_in[1];
    if (n_in >= 2 && in_sizes[0] == BN && in_sizes[1] == 3 * BN) {
        const float* tmp = pos; pos = f; f = tmp;   // defensive input order
    }
    float* out = (float*)d_out;

    k_zero<<<(TOTC + 1023) / 1024, 1024>>>();
    k_hist<<<BN / 512, 512>>>(pos);
    k_scan<<<1, 1024>>>();
    k_scatter<<<BN / 512, 512>>>(pos, f);
    k_main<<<NBLK, 256>>>(out);
}

// round 13
// speedup vs baseline: 1.2895x; 1.2895x over previous
#include <cuda_runtime.h>

// DirichletLoss: ball query (r=0.15, K=32 nearest within radius) + neighbor
// feature variance, mean over all B*N queries, *0.5.
//
// 2-kernel pipeline (graph-capturable, scratch in __device__ globals):
//   k_build : per-batch block — smem histogram over anisotropic grid
//             7(z) x 7(y) x 32(x), hierarchical smem scan (2 cells/thread),
//             counting-sort into float4(x,y,z,f) cell-major; global offsets
//   k_main  : warp-per-query, single pass. Packed keys
//             uint32 = (d2 bits & ~0xFFF) | batch-local index.
//             First chunk: 32-lane bitonic sort free-fills all 32 slots.
//             Later chunks: ballot-filtered sorted insert (2 shfl each).
//             x-range clipped to [p.x-r, p.x+r]; stencil rows skipped when
//             their min possible distance can't beat the current cutoff.
//             Block partial -> last-block deterministic reduction -> out.
//
// All candidate ranges are clamped so every loop terminates even if the
// offset table were corrupt (bugs become wrong answers, not hangs).

#define FULLMASK 0xFFFFFFFFu

constexpr int   B    = 8;
constexpr int   N    = 4096;
constexpr int   BN   = B * N;
constexpr int   GDY  = 7;               // y,z cells (size 0.15 = r)
constexpr int   GDX  = 32;              // fine x cells (size 1/32)
constexpr int   NC   = GDY * GDY * GDX; // 1568 cells per batch
constexpr int   TOTC = B * NC;
constexpr int   NBLK = BN / 8;          // k_main blocks (8 warps each)
constexpr float R        = 0.15f;
constexpr float R2       = 0.15f * 0.15f;
constexpr float CELLYZ   = 0.15f;
constexpr float INV_YZ   = 1.0f / 0.15f;
constexpr unsigned SENT  = 0xFFFFFFFFu;

__device__ int      g_off[TOTC + 1];
__device__ float4   g_pts[BN];          // (x,y,z,f) sorted by global cell id
__device__ float    g_var[NBLK];        // per-block partial sums
__device__ unsigned g_done;             // last-block ticket

__device__ __forceinline__ int cellyz(float v) {
    int c = (int)(v * INV_YZ);
    c = c < 0 ? 0 : c;
    return c > GDY - 1 ? GDY - 1 : c;
}
__device__ __forceinline__ int cellx(float v) {
    int c = (int)(v * (float)GDX);
    c = c < 0 ? 0 : c;
    return c > GDX - 1 ? GDX - 1 : c;
}

// One block per batch: smem histogram -> hierarchical scan -> scatter.
__global__ void __launch_bounds__(1024) k_build(const float* __restrict__ pos,
                                                const float* __restrict__ f) {
    __shared__ int cnt[NC];
    __shared__ int cur[NC];             // fill cursors (exclusive offsets)
    __shared__ int wt[32], wb[32];
    int b = blockIdx.x, t = threadIdx.x;
    int lane = t & 31, w = t >> 5;
    int base = b * N;

    if (b == 0 && t == 0) g_done = 0;   // reset reduction ticket
    for (int i = t; i < NC; i += 1024) cnt[i] = 0;
    __syncthreads();

    float mx[4], my[4], mz[4], mf[4];
    int   mc[4];
    #pragma unroll
    for (int k = 0; k < 4; k++) {
        int gi = base + t + k * 1024;
        float x = pos[3 * gi], y = pos[3 * gi + 1], z = pos[3 * gi + 2];
        mx[k] = x; my[k] = y; mz[k] = z; mf[k] = f[gi];
        int c = (cellyz(z) * GDY + cellyz(y)) * GDX + cellx(x);
        mc[k] = c;
        atomicAdd(&cnt[c], 1);
    }
    __syncthreads();

    // Exclusive scan over NC=1568 smem counts: 2 cells/thread.
    int i0 = 2 * t, i1 = 2 * t + 1;
    int c0 = (i0 < NC) ? cnt[i0] : 0;
    int c1 = (i1 < NC) ? cnt[i1] : 0;
    int s  = c0 + c1;
    int v  = s;
    #pragma unroll
    for (int d = 1; d < 32; d <<= 1) {
        int u = __shfl_up_sync(FULLMASK, v, d);
        if (lane >= d) v += u;
    }
    if (lane == 31) wt[w] = v;
    __syncthreads();
    if (w == 0) {
        int x = wt[lane];
        int vv = x;
        #pragma unroll
        for (int d = 1; d < 32; d <<= 1) {
            int u = __shfl_up_sync(FULLMASK, vv, d);
            if (lane >= d) vv += u;
        }
        wb[lane] = vv - x;              // exclusive warp base
    }
    __syncthreads();
    int run = wb[w] + v - s;            // thread's exclusive start
    if (i0 < NC) { cur[i0] = run; g_off[b * NC + i0] = base + run; run += c0; }
    if (i1 < NC) { cur[i1] = run; g_off[b * NC + i1] = base + run; }
    if (b == B - 1 && t == 1023) g_off[TOTC] = BN;
    __syncthreads();

    #pragma unroll
    for (int k = 0; k < 4; k++) {
        int dst = base + atomicAdd(&cur[mc[k]], 1);
        if (dst >= 0 && dst < BN)
            g_pts[dst] = make_float4(mx[k], my[k], mz[k], mf[k]);
    }
}

// One warp per query; bitonic first-chunk fill + sorted-insert top-32.
__global__ void __launch_bounds__(256) k_main(float* __restrict__ out) {
    __shared__ float  swarp[8];
    __shared__ double sd[256];
    __shared__ bool   amLast;
    int lane = threadIdx.x & 31;
    int wid  = threadIdx.x >> 5;
    int q    = blockIdx.x * 8 + wid;

    float4 p = g_pts[q];
    int b    = q >> 12;                 // build is batch-major -> contiguous
    int base = b * N;
    const float4* pbase = g_pts + base;
    int cy = cellyz(p.y), cz = cellyz(p.z);
    int xl = cellx(p.x - R), xh = cellx(p.x + R);   // exact x window

    // Key domain: pk = (d2 bits & ~0xFFF) | local index (12 bits).
    const unsigned cutR  = (__float_as_uint(R2) & 0xFFFFF000u) | 0xFFFu;
    const unsigned EMPTY = cutR + 1;

    // Lane-parallel preload of the 9 stencil rows: range + min-distance
    // key. Center row (dz=0,dy=0) first so the cutoff tightens early.
    int rs0 = 0, rs1 = 0;
    unsigned rmk = SENT;                // truncated key of rowmin^2
    {
        const signed char DZ[9] = {0, 0, 0, -1, -1, -1, 1, 1, 1};
        const signed char DY[9] = {0, -1, 1, 0, -1, 1, 0, -1, 1};
        if (lane < 9) {
            int z = cz + DZ[lane], y = cy + DY[lane];
            if (z >= 0 && z < GDY && y >= 0 && y < GDY) {
                int rb = b * NC + (z * GDY + y) * GDX;
                int a0 = g_off[rb + xl] - base;
                int a1 = g_off[rb + xh + 1] - base;  // contiguous x cells
                a0 = a0 < 0 ? 0 : a0;                // termination guards
                a1 = a1 > N ? N : a1;
                rs0 = a0;
                rs1 = a1 < a0 ? a0 : a1;
                float dym = fmaxf(0.0f, fmaxf(y * CELLYZ - p.y,
                                              p.y - (y + 1) * CELLYZ));
                float dzm = fmaxf(0.0f, fmaxf(z * CELLYZ - p.z,
                                              p.z - (z + 1) * CELLYZ));
                float rm2 = fmaf(dym, dym, dzm * dzm);
                rmk = __float_as_uint(rm2) & 0xFFFFF000u;
            }
        }
    }

    unsigned kk = SENT;                 // lane-sorted ascending packed keys
    unsigned cutoffC = EMPTY;           // min(lane31 key, EMPTY)
    bool firstChunk = true;             // warp-uniform

    #pragma unroll 1
    for (int r = 0; r < 9; r++) {
        unsigned rk = __shfl_sync(FULLMASK, rmk, r);
        if (rk >= cutoffC) continue;    // row can't beat current 32nd
        int l0 = __shfl_sync(FULLMASK, rs0, r);
        int l1 = __shfl_sync(FULLMASK, rs1, r);
        for (int c0 = l0; c0 < l1; c0 += 32) {
            int l = c0 + lane;
            unsigned pk = SENT;
            if (l < l1) {
                float4 c = pbase[l];
                float dx = c.x - p.x, dy = c.y - p.y, dz = c.z - p.z;
                float d2 = fmaf(dx, dx, fmaf(dy, dy, dz * dz));
                pk = (__float_as_uint(d2) & 0xFFFFF000u) | (unsigned)l;
            }
            if (firstChunk) {
                // Full-warp bitonic ascending sort free-fills all 32 slots.
                unsigned v = pk;
                #pragma unroll
                for (int k = 2; k <= 32; k <<= 1) {
                    #pragma unroll
                    for (int j = k >> 1; j > 0; j >>= 1) {
                        unsigned o = __shfl_xor_sync(FULLMASK, v, j);
                        bool up    = ((lane & k) == 0);
                        bool lower = ((lane & j) == 0);
                        unsigned mn = o < v ? o : v;
                        unsigned mx = o < v ? v : o;
                        v = (lower == up) ? mn : mx;
                    }
                }
                kk = v;
                unsigned k31 = __shfl_sync(FULLMASK, kk, 31);
                cutoffC = k31 < EMPTY ? k31 : EMPTY;
                firstChunk = false;
                continue;
            }
            unsigned want = __ballot_sync(FULLMASK, pk < cutoffC);
            if (want) {
                do {
                    int src = __ffs(want) - 1;
                    want &= want - 1;
                    unsigned v  = __shfl_sync(FULLMASK, pk, src);
                    unsigned pd = __shfl_up_sync(FULLMASK, kk, 1);
                    if (lane == 0) pd = 0u;
                    if (kk > v) kk = pd > v ? pd : v;   // sorted insert
                } while (want);
                unsigned k31 = __shfl_sync(FULLMASK, kk, 31);
                cutoffC = k31 < EMPTY ? k31 : EMPTY;
            }
        }
    }

    // Epilogue: each lane holds one selected neighbor (or none).
    float acc = 0.0f;
    if (kk <= cutR) {
        int l = (int)(kk & 0xFFFu);
        float fj = pbase[l].w;
        float df = p.w - fj;
        acc = df * df;
    }
    #pragma unroll
    for (int o = 16; o; o >>= 1) acc += __shfl_xor_sync(FULLMASK, acc, o);
    if (lane == 0) swarp[wid] = acc;
    __syncthreads();
    if (threadIdx.x == 0) {
        float s = 0.0f;
        #pragma unroll
        for (int w = 0; w < 8; w++) s += swarp[w];
        g_var[blockIdx.x] = s;
    }

    // ---- last-block deterministic reduction ----
    __threadfence();
    if (threadIdx.x == 0)
        amLast = (atomicAdd(&g_done, 1u) == (unsigned)(NBLK - 1));
    __syncthreads();
    if (amLast) {
        double a = 0.0;
        for (int i = threadIdx.x; i < NBLK; i += 256) a += (double)g_var[i];
        sd[threadIdx.x] = a;
        __syncthreads();
        for (int d = 128; d; d >>= 1) {
            if (threadIdx.x < d) sd[threadIdx.x] += sd[threadIdx.x + d];
            __syncthreads();
        }
        if (threadIdx.x == 0) out[0] = (float)(0.5 * sd[0] / (double)BN);
    }
}

extern "C" void kernel_launch(void* const* d_in, const int* in_sizes, int n_in,
                              void* d_out, int out_size) {
    const float* pos = (const float*)d_in[0];
    const float* f   = (const float*)d_in[1];
    if (n_in >= 2 && in_sizes[0] == BN && in_sizes[1] == 3 * BN) {
        const float* tmp = pos; pos = f; f = tmp;   // defensive input order
    }
    float* out = (float*)d_out;

    k_build<<<B, 1024>>>(pos, f);
    k_main<<<NBLK, 256>>>(out);
}